// round 12
// baseline (speedup 1.0000x reference)
#include <cuda_runtime.h>
#include <math.h>

#define FDIM 128
#define GMAX 50000
#define SEGB 64          // segments per MLP block
#define PAD  68          // spT row stride (floats): 16B-aligned, conflict-free

// ---------------- device scratch (zero-initialized .bss; self-restoring) ----------------
// g_pool starts zero (.bss); the MLP kernel re-zeroes it after consuming it,
// so every graph replay sees zeros again. L2-resident (25.6 MB << 126 MB L2).
__device__ float g_pool[(size_t)GMAX * FDIM];

__device__ __forceinline__ float tanh_fast(float x) {
    float r;
    asm("tanh.approx.f32 %0, %1;" : "=f"(r) : "f"(x));
    return r;
}

typedef unsigned long long ull;

__device__ __forceinline__ ull dup2(float x) {           // {x, x} as f32x2
    ull r;
    asm("mov.b64 %0, {%1, %1};" : "=l"(r) : "f"(x));
    return r;
}
__device__ __forceinline__ void fma2(ull& d, ull a, ull b) {  // d = a*b + d (lanewise f32)
    asm("fma.rn.f32x2 %0, %1, %2, %3;" : "=l"(d) : "l"(a), "l"(b), "l"(d));
}
__device__ __forceinline__ void unpack2(float& lo, float& hi, ull v) {
    asm("mov.b64 {%0, %1}, %2;" : "=f"(lo), "=f"(hi) : "l"(v));
}

// ---------------- kernel 1: stream h in node order, scatter-add into L2 pool ----------------
// Perfectly coalesced, sequential h reads (row-buffer friendly). Each node row is
// reduced into pooled[seg] with fire-and-forget vector reductions (no return latency).
__global__ void __launch_bounds__(256) stream_pool_kernel(
    const float* __restrict__ h,
    const void*  __restrict__ seg,
    int N)
{
    __shared__ int s_is64;
    if (threadIdx.x == 0) {
        // int64 ids < 2^32 have zero high words; 64 random int32 ids all-zero: p ~ 0
        const unsigned int* w = (const unsigned int*)seg;
        unsigned int acc = 0;
        #pragma unroll
        for (int k = 0; k < 64; k++) acc |= w[2 * k + 1];
        s_is64 = (acc == 0u) ? 1 : 0;
    }
    __syncthreads();
    const int is64 = s_is64;

    const int warp = threadIdx.x >> 5;
    const int lane = threadIdx.x & 31;
    const int base = (blockIdx.x * 8 + warp) * 32;   // 32 consecutive nodes per warp
    if (base >= N) return;                           // uniform per warp
    const int cnt = min(32, N - base);

    // lane l holds seg id of node base+l (coalesced read)
    int sid = 0;
    if (lane < cnt) {
        sid = is64 ? (int)((const long long*)seg)[base + lane]
                   : ((const int*)seg)[base + lane];
    }

    // stream 32 rows: sequential LDG.128 (full warp = 512B contiguous), then
    // red.global.add.v4.f32 into the L2-resident pooled row (no return value).
    #pragma unroll 4
    for (int j = 0; j < 32; j++) {
        if (j >= cnt) break;
        const int s = __shfl_sync(0xffffffffu, sid, j);
        float4 v = __ldcs((const float4*)(h + (size_t)(base + j) * FDIM) + lane);
        float* dst = g_pool + (size_t)s * FDIM + lane * 4;
        asm volatile("red.global.add.v4.f32 [%0], {%1, %2, %3, %4};"
                     :: "l"(dst), "f"(v.x), "f"(v.y), "f"(v.z), "f"(v.w)
                     : "memory");
    }
}

// ---------------- kernel 2: MLP head, 64 segments/block, f32x2 FMA ----------------
// Transposed pooled tile spT[k][s] in smem. Warp w owns segs 8w..8w+7 and
// (per lane l) columns 4l..4l+3. Per k: 1 coalesced LDG.128 of the W1 row +
// 2 broadcast LDS.128 (8 seg values = 4 f32x2 pairs, reinterpreted in place) +
// 16 fma.rn.f32x2 -> 32 FMA lanes in 23 issue slots.
__global__ void __launch_bounds__(256) mlp_kernel(
    const float* __restrict__ W1,   // [128,128] row-major: W1[k][c]
    const float* __restrict__ b1,   // [128]
    const float* __restrict__ W2,   // [128]
    const float* __restrict__ b2,   // [1]
    float* __restrict__ y, int G)
{
    __shared__ float spT[FDIM][PAD];    // transposed pooled tile (34.8 KB)
    __shared__ float sy[SEGB];

    const int tid  = threadIdx.x;
    const int warp = tid >> 5;
    const int lane = tid & 31;
    const int gbase = blockIdx.x * SEGB;

    // ---- transpose-load pooled tile; zero g_pool behind us ----
    // lanes -> consecutive s: conflict-free STS (bank = (68k+s)&31, s consecutive).
    // g_pool read is 16B-per-thread strided, but the pool is L2-resident.
    const float4 z4 = make_float4(0.f, 0.f, 0.f, 0.f);
    #pragma unroll
    for (int it = 0; it < 8; it++) {
        int idx = it * 256 + tid;       // 0..2047
        int k4  = idx >> 6;             // float4 chunk 0..31
        int s   = idx & 63;
        int g   = gbase + s;
        float4 v = z4;
        if (g < G) {
            float4* p = (float4*)(g_pool + (size_t)g * FDIM) + k4;
            v = *p;
            *p = z4;                    // self-restore for the next replay
        }
        spT[4 * k4 + 0][s] = v.x;
        spT[4 * k4 + 1][s] = v.y;
        spT[4 * k4 + 2][s] = v.z;
        spT[4 * k4 + 3][s] = v.w;
    }
    __syncthreads();

    // ---- register-tiled GEMM: 8 segs (f32x2-paired) x 4 cols per thread ----
    float4 bb = __ldg((const float4*)b1 + lane);    // b1[4l..4l+3]
    ull acc[4][4];                                  // [segpair][col]
    {
        ull i0 = dup2(bb.x), i1 = dup2(bb.y), i2 = dup2(bb.z), i3 = dup2(bb.w);
        #pragma unroll
        for (int qp = 0; qp < 4; qp++) {
            acc[qp][0] = i0; acc[qp][1] = i1; acc[qp][2] = i2; acc[qp][3] = i3;
        }
    }

    const int s0 = warp * 8;
    #pragma unroll 4
    for (int k = 0; k < FDIM; k++) {
        float4 wv = __ldg((const float4*)(W1 + k * FDIM) + lane);   // W1[k][4l..4l+3]
        ull w0 = dup2(wv.x), w1 = dup2(wv.y), w2d = dup2(wv.z), w3 = dup2(wv.w);
        // 8 consecutive seg values -> 4 f32x2 pairs, no packing needed
        ulonglong2 qa = *(const ulonglong2*)&spT[k][s0];        // {s0,s1},{s2,s3}
        ulonglong2 qb = *(const ulonglong2*)&spT[k][s0 + 4];    // {s4,s5},{s6,s7}
        fma2(acc[0][0], qa.x, w0); fma2(acc[0][1], qa.x, w1);
        fma2(acc[0][2], qa.x, w2d); fma2(acc[0][3], qa.x, w3);
        fma2(acc[1][0], qa.y, w0); fma2(acc[1][1], qa.y, w1);
        fma2(acc[1][2], qa.y, w2d); fma2(acc[1][3], qa.y, w3);
        fma2(acc[2][0], qb.x, w0); fma2(acc[2][1], qb.x, w1);
        fma2(acc[2][2], qb.x, w2d); fma2(acc[2][3], qb.x, w3);
        fma2(acc[3][0], qb.y, w0); fma2(acc[3][1], qb.y, w1);
        fma2(acc[3][2], qb.y, w2d); fma2(acc[3][3], qb.y, w3);
    }

    // ---- epilogue: tanh, dot with W2 over this thread's 4 cols, warp-reduce ----
    float4 w2 = __ldg((const float4*)W2 + lane);
    const float w2a[4] = {w2.x, w2.y, w2.z, w2.w};
    float psum[8];
    #pragma unroll
    for (int qp = 0; qp < 4; qp++) {
        float pe = 0.f, po = 0.f;
        #pragma unroll
        for (int c = 0; c < 4; c++) {
            float lo, hi;
            unpack2(lo, hi, acc[qp][c]);
            pe = fmaf(tanh_fast(lo), w2a[c], pe);
            po = fmaf(tanh_fast(hi), w2a[c], po);
        }
        psum[2 * qp]     = pe;
        psum[2 * qp + 1] = po;
    }
    #pragma unroll
    for (int off = 16; off; off >>= 1) {
        #pragma unroll
        for (int s = 0; s < 8; s++)
            psum[s] += __shfl_down_sync(0xffffffffu, psum[s], off);
    }
    if (lane == 0) {
        #pragma unroll
        for (int s = 0; s < 8; s++) sy[s0 + s] = psum[s];
    }
    __syncthreads();

    if (tid < SEGB) {
        int g = gbase + tid;
        if (g < G) y[g] = sy[tid] + __ldg(b2);
    }
}

// ---------------- launch ----------------
extern "C" void kernel_launch(void* const* d_in, const int* in_sizes, int n_in,
                              void* d_out, int out_size) {
    const float* h   = (const float*)d_in[0];
    const void*  seg = d_in[1];
    const int N = in_sizes[0] / FDIM;
    const int G = out_size;          // OUT = 1

    int iw = -1;
    for (int i = 2; i < n_in; i++) {
        if (in_sizes[i] == FDIM * FDIM) { iw = i; break; }
    }
    const float* W1 = (const float*)d_in[iw];
    const float* b1 = (const float*)d_in[iw + 1];
    const float* W2 = (const float*)d_in[iw + 2];
    const float* b2 = (const float*)d_in[iw + 3];
    float* y = (float*)d_out;

    const int nodes_per_blk = 8 * 32;    // 8 warps x 32 nodes
    stream_pool_kernel<<<(N + nodes_per_blk - 1) / nodes_per_blk, 256>>>(h, seg, N);
    mlp_kernel<<<(G + SEGB - 1) / SEGB, 256>>>(W1, b1, W2, b2, y, G);
}